// round 4
// baseline (speedup 1.0000x reference)
#include <cuda_runtime.h>

#define Bq 4
#define Vq 50000
#define Cq 160
#define PAIRS 25000          // Vq/2
#define P_BLK 64             // vertex-pairs per block
#define V_BLK 128            // vertices per block
#define NTHR 256             // P_BLK * 4 (q-split)

// G table: per node-column c, 12 components j (9 R rows, 3 t), 4 batches packed:
// g_table[c*48 + j*4 + b]. Align 16 for ulonglong2 reads.
__device__ __align__(16) float g_table[Cq * 48];

// ---------------- Precompute kernel: 640 threads ----------------
__global__ void precompute_kernel(const float* __restrict__ X,
                                  const float* __restrict__ Vn,
                                  const float* __restrict__ r6,
                                  const int* __restrict__ idx) {
    int i = blockIdx.x * blockDim.x + threadIdx.x;
    if (i >= Bq * Cq) return;
    int b = i / Cq, c = i % Cq;

    const float* d6 = r6 + (size_t)(b * Cq + c) * 6;
    float a1x = d6[0], a1y = d6[1], a1z = d6[2];
    float a2x = d6[3], a2y = d6[4], a2z = d6[5];

    float n1 = fmaxf(sqrtf(a1x*a1x + a1y*a1y + a1z*a1z), 1e-8f);
    float b1x = a1x / n1, b1y = a1y / n1, b1z = a1z / n1;
    float dt = b1x*a2x + b1y*a2y + b1z*a2z;
    float px = a2x - dt*b1x, py = a2y - dt*b1y, pz = a2z - dt*b1z;
    float n2 = fmaxf(sqrtf(px*px + py*py + pz*pz), 1e-8f);
    float b2x = px / n2, b2y = py / n2, b2z = pz / n2;
    float b3x = b1y*b2z - b1z*b2y;
    float b3y = b1z*b2x - b1x*b2z;
    float b3z = b1x*b2y - b1y*b2x;

    float R[3][3] = {{b1x, b1y, b1z}, {b2x, b2y, b2z}, {b3x, b3y, b3z}};

    int vi = idx[c];
    vi = max(0, min(Vq - 1, vi));
    const float* xc = X + ((size_t)b * Vq + vi) * 3;
    float cen[3] = {xc[0], xc[1], xc[2]};
    const float* vn = Vn + (size_t)(b * Cq + c) * 3;

    #pragma unroll
    for (int k = 0; k < 3; k++) {
        float t = cen[k] + vn[k]
                - (R[k][0]*cen[0] + R[k][1]*cen[1] + R[k][2]*cen[2]);
        g_table[c*48 + (9 + k)*4 + b] = t;
        #pragma unroll
        for (int d = 0; d < 3; d++)
            g_table[c*48 + (k*3 + d)*4 + b] = R[k][d];
    }
}

// ---------------- f32x2 helpers ----------------
__device__ __forceinline__ void fma2(unsigned long long& acc,
                                     unsigned long long a,
                                     unsigned long long b) {
    asm("fma.rn.f32x2 %0, %1, %2, %0;" : "+l"(acc) : "l"(a), "l"(b));
}
__device__ __forceinline__ void add2(unsigned long long& acc,
                                     unsigned long long a) {
    asm("add.rn.f32x2 %0, %0, %1;" : "+l"(acc) : "l"(a));
}
__device__ __forceinline__ unsigned long long dup2(float w) {
    unsigned long long r;
    asm("mov.b64 %0, {%1, %1};" : "=l"(r) : "f"(w));
    return r;
}
__device__ __forceinline__ float2 unpk(unsigned long long a) {
    float2 r;
    asm("mov.b64 {%0, %1}, %2;" : "=f"(r.x), "=f"(r.y) : "l"(a));
    return r;
}
__device__ __forceinline__ unsigned long long shfl_dn_u64(unsigned long long x, int d) {
    unsigned int lo = (unsigned int)x, hi = (unsigned int)(x >> 32);
    lo = __shfl_down_sync(0xffffffffu, lo, d);
    hi = __shfl_down_sync(0xffffffffu, hi, d);
    return ((unsigned long long)hi << 32) | lo;
}

// ---------------- Epilogue: out[b,v,:] = M·x + t ----------------
// acc layout: acc[2*j] = comp j batches (0,1); acc[2*j+1] = batches (2,3)
__device__ __forceinline__ void finish(int v,
                                       const unsigned long long* acc,
                                       const float* __restrict__ X,
                                       float* __restrict__ out) {
    #pragma unroll
    for (int b = 0; b < 4; b++) {
        float m[12];
        #pragma unroll
        for (int j = 0; j < 12; j++) {
            float2 u = unpk(acc[2*j + (b >> 1)]);
            m[j] = (b & 1) ? u.y : u.x;
        }
        const float* xp = X + ((size_t)b * Vq + v) * 3;
        float x0 = xp[0], x1 = xp[1], x2 = xp[2];
        float* op = out + ((size_t)b * Vq + v) * 3;
        #pragma unroll
        for (int k = 0; k < 3; k++)
            op[k] = m[9 + k] + m[3*k]*x0 + m[3*k + 1]*x1 + m[3*k + 2]*x2;
    }
}

// ---------------- Main kernel ----------------
// Thread layout: pair_local = tid>>2 (0..63), q = tid&3 (C-quarter).
// Warp = 8 pairs x 4 quarters; combine across q via shfl_down 1,2.
// W rows for the block's 128 vertices staged coalesced into smem.
__global__ void __launch_bounds__(NTHR)
main_kernel(const float* __restrict__ W,
            const float* __restrict__ X,
            float* __restrict__ out) {
    extern __shared__ __align__(16) unsigned char smem_raw[];
    float* sw = (float*)smem_raw;                               // 128*160 floats, 80KB
    unsigned long long* sg =
        (unsigned long long*)(smem_raw + V_BLK * Cq * 4);       // 3840 u64, 30KB

    // Stage G (packed f32x2 pairs)
    {
        const unsigned long long* g2 = (const unsigned long long*)g_table;
        #pragma unroll 4
        for (int i = threadIdx.x; i < Cq * 24; i += NTHR) sg[i] = g2[i];
    }
    // Stage W rows coalesced: 128 rows x 40 float4
    {
        int v_base = blockIdx.x * V_BLK;
        #pragma unroll 4
        for (int i = threadIdx.x; i < V_BLK * (Cq / 4); i += NTHR) {
            int vl = i / (Cq / 4), f4 = i % (Cq / 4);
            int vg = min(v_base + vl, Vq - 1);
            float4 w = *(const float4*)(W + (size_t)vg * Cq + f4 * 4);
            *(float4*)(sw + vl * Cq + f4 * 4) = w;
        }
    }
    __syncthreads();

    int pl = threadIdx.x >> 2;          // pair within block
    int q  = threadIdx.x & 3;           // C-quarter
    int pair = blockIdx.x * P_BLK + pl;
    bool valid = pair < PAIRS;

    unsigned long long acc0[24], acc1[24];
    #pragma unroll
    for (int j = 0; j < 24; j++) { acc0[j] = 0ull; acc1[j] = 0ull; }

    const float4* w0 = (const float4*)(sw + (2 * pl)     * Cq + q * 40);
    const float4* w1 = (const float4*)(sw + (2 * pl + 1) * Cq + q * 40);
    const ulonglong2* gbase = ((const ulonglong2*)sg) + (size_t)q * 40 * 12;

    #pragma unroll 2
    for (int grp = 0; grp < 10; grp++) {    // 10 groups of 4 columns = 40 cols
        float4 wa = w0[grp];
        float4 wb = w1[grp];
        float was[4] = {wa.x, wa.y, wa.z, wa.w};
        float wbs[4] = {wb.x, wb.y, wb.z, wb.w};
        #pragma unroll
        for (int s = 0; s < 4; s++) {
            unsigned long long W0 = dup2(was[s]);
            unsigned long long W1 = dup2(wbs[s]);
            const ulonglong2* gr = gbase + (grp * 4 + s) * 12;
            #pragma unroll
            for (int j = 0; j < 12; j++) {
                ulonglong2 g = gr[j];        // (b0,b1), (b2,b3)
                fma2(acc0[2*j],     W0, g.x);
                fma2(acc0[2*j + 1], W0, g.y);
                fma2(acc1[2*j],     W1, g.x);
                fma2(acc1[2*j + 1], W1, g.y);
            }
        }
    }

    // Combine C-quarters across q lanes (tree: +1 then +2)
    #pragma unroll
    for (int j = 0; j < 24; j++) {
        add2(acc0[j], shfl_dn_u64(acc0[j], 1));
        add2(acc1[j], shfl_dn_u64(acc1[j], 1));
        add2(acc0[j], shfl_dn_u64(acc0[j], 2));
        add2(acc1[j], shfl_dn_u64(acc1[j], 2));
    }

    if (q == 0 && valid) {
        finish(2 * pair,     acc0, X, out);
        finish(2 * pair + 1, acc1, X, out);
    }
}

// ---------------- launch ----------------
extern "C" void kernel_launch(void* const* d_in, const int* in_sizes, int n_in,
                              void* d_out, int out_size) {
    const float* X   = (const float*)d_in[0];
    const float* Vn  = (const float*)d_in[1];
    const float* r6  = (const float*)d_in[2];
    const float* W   = (const float*)d_in[3];
    const int*   idx = (const int*)d_in[4];   // JAX x64-disabled: int64 -> int32
    float* out = (float*)d_out;

    precompute_kernel<<<(Bq * Cq + 127) / 128, 128>>>(X, Vn, r6, idx);

    const int smem_bytes = V_BLK * Cq * 4 + Cq * 24 * 8;   // 80KB + 30KB
    static bool attr_set = false;
    // setting an attribute is idempotent and capture-safe; call every time
    cudaFuncSetAttribute(main_kernel,
                         cudaFuncAttributeMaxDynamicSharedMemorySize, smem_bytes);
    (void)attr_set;

    int grid = (PAIRS + P_BLK - 1) / P_BLK;   // 391 blocks
    main_kernel<<<grid, NTHR, smem_bytes>>>(W, X, out);
}

// round 5
// speedup vs baseline: 2.6767x; 2.6767x over previous
#include <cuda_runtime.h>

#define Bq 4
#define Vq 50000
#define Cq 160
#define PAIRS 25000          // Vq/2
#define P_BLK 16             // vertex-pairs per block
#define V_BLK 32             // vertices per block
#define NTHR 128             // P_BLK * 2(h) * 4(q)
#define REG_U64 482          // u64 per (q,h) G region = 3856B (odd*16 pad)

// G table (gmem): float at [c*48 + h*24 + j*2 + (b&1)], h = b>>1.
// As u64: [c*24 + h*12 + j] = (batch 2h, batch 2h+1) for component j.
__device__ __align__(16) float g_table[Cq * 48];

// ---------------- Precompute kernel: 640 threads ----------------
__global__ void precompute_kernel(const float* __restrict__ X,
                                  const float* __restrict__ Vn,
                                  const float* __restrict__ r6,
                                  const int* __restrict__ idx) {
    int i = blockIdx.x * blockDim.x + threadIdx.x;
    if (i >= Bq * Cq) return;
    int b = i / Cq, c = i % Cq;

    const float* d6 = r6 + (size_t)(b * Cq + c) * 6;
    float a1x = d6[0], a1y = d6[1], a1z = d6[2];
    float a2x = d6[3], a2y = d6[4], a2z = d6[5];

    float n1 = fmaxf(sqrtf(a1x*a1x + a1y*a1y + a1z*a1z), 1e-8f);
    float b1x = a1x / n1, b1y = a1y / n1, b1z = a1z / n1;
    float dt = b1x*a2x + b1y*a2y + b1z*a2z;
    float px = a2x - dt*b1x, py = a2y - dt*b1y, pz = a2z - dt*b1z;
    float n2 = fmaxf(sqrtf(px*px + py*py + pz*pz), 1e-8f);
    float b2x = px / n2, b2y = py / n2, b2z = pz / n2;
    float b3x = b1y*b2z - b1z*b2y;
    float b3y = b1z*b2x - b1x*b2z;
    float b3z = b1x*b2y - b1y*b2x;

    float R[3][3] = {{b1x, b1y, b1z}, {b2x, b2y, b2z}, {b3x, b3y, b3z}};

    int vi = idx[c];
    vi = max(0, min(Vq - 1, vi));
    const float* xc = X + ((size_t)b * Vq + vi) * 3;
    float cen[3] = {xc[0], xc[1], xc[2]};
    const float* vn = Vn + (size_t)(b * Cq + c) * 3;

    int h = b >> 1, lo = b & 1;
    #pragma unroll
    for (int k = 0; k < 3; k++) {
        float t = cen[k] + vn[k]
                - (R[k][0]*cen[0] + R[k][1]*cen[1] + R[k][2]*cen[2]);
        g_table[c*48 + h*24 + (9 + k)*2 + lo] = t;
        #pragma unroll
        for (int d = 0; d < 3; d++)
            g_table[c*48 + h*24 + (k*3 + d)*2 + lo] = R[k][d];
    }
}

// ---------------- f32x2 helpers ----------------
__device__ __forceinline__ void fma2(unsigned long long& acc,
                                     unsigned long long a,
                                     unsigned long long b) {
    asm("fma.rn.f32x2 %0, %1, %2, %0;" : "+l"(acc) : "l"(a), "l"(b));
}
__device__ __forceinline__ void add2(unsigned long long& acc,
                                     unsigned long long a) {
    asm("add.rn.f32x2 %0, %0, %1;" : "+l"(acc) : "l"(a));
}
__device__ __forceinline__ unsigned long long dup2(float w) {
    unsigned long long r;
    asm("mov.b64 %0, {%1, %1};" : "=l"(r) : "f"(w));
    return r;
}
__device__ __forceinline__ float2 unpk(unsigned long long a) {
    float2 r;
    asm("mov.b64 {%0, %1}, %2;" : "=f"(r.x), "=f"(r.y) : "l"(a));
    return r;
}
__device__ __forceinline__ unsigned long long shfl_dn_u64(unsigned long long x, int d) {
    unsigned int lo = (unsigned int)x, hi = (unsigned int)(x >> 32);
    lo = __shfl_down_sync(0xffffffffu, lo, d);
    hi = __shfl_down_sync(0xffffffffu, hi, d);
    return ((unsigned long long)hi << 32) | lo;
}

// ---------------- Epilogue for one vertex, one batch-pair h ----------------
__device__ __forceinline__ void finish(int v, int h,
                                       const unsigned long long* acc,
                                       const float* __restrict__ X,
                                       float* __restrict__ out) {
    #pragma unroll
    for (int b01 = 0; b01 < 2; b01++) {
        int b = 2 * h + b01;
        float m[12];
        #pragma unroll
        for (int j = 0; j < 12; j++) {
            float2 u = unpk(acc[j]);
            m[j] = b01 ? u.y : u.x;
        }
        const float* xp = X + ((size_t)b * Vq + v) * 3;
        float x0 = xp[0], x1 = xp[1], x2 = xp[2];
        float* op = out + ((size_t)b * Vq + v) * 3;
        #pragma unroll
        for (int k = 0; k < 3; k++)
            op[k] = m[9 + k] + m[3*k]*x0 + m[3*k + 1]*x1 + m[3*k + 2]*x2;
    }
}

// ---------------- Main kernel ----------------
// tid = pl*8 + h*4 + q. pl: vertex-pair (2 vertices), h: batch-pair, q: C-quarter.
// W (32 rows x 160 f) staged coalesced in smem; G swizzled into 8 (q,h) regions
// of 3856B so the 8 lane-group LDS addresses are bank-distinct.
__global__ void __launch_bounds__(NTHR, 4)
main_kernel(const float* __restrict__ W,
            const float* __restrict__ X,
            float* __restrict__ out) {
    extern __shared__ __align__(16) unsigned char smem_raw[];
    float* sw = (float*)smem_raw;                                   // 32*160 f = 20480B
    unsigned long long* sg =
        (unsigned long long*)(smem_raw + V_BLK * Cq * 4);           // 8*482 u64 = 30856B

    // Stage W coalesced: 32 rows x 40 float4
    {
        int vbase = blockIdx.x * V_BLK;
        float4* swf4 = (float4*)sw;
        const float4* wf4 = (const float4*)W;
        #pragma unroll 5
        for (int i = threadIdx.x; i < V_BLK * 40; i += NTHR) {
            int r = i / 40, c4 = i % 40;
            int vg = min(vbase + r, Vq - 1);
            swf4[i] = wf4[(size_t)vg * 40 + c4];
        }
    }
    // Stage G with (q,h)-region swizzle
    {
        const unsigned long long* g2 = (const unsigned long long*)g_table;
        #pragma unroll 4
        for (int i = threadIdx.x; i < Cq * 24; i += NTHR) {
            int c = i / 24, rem = i % 24;
            int h = rem / 12, j = rem % 12;
            int r = (c / 40) * 2 + h, cc = c % 40;
            sg[r * REG_U64 + cc * 12 + j] = g2[i];
        }
    }
    __syncthreads();

    int pl = threadIdx.x >> 3;
    int h  = (threadIdx.x >> 2) & 1;
    int q  = threadIdx.x & 3;
    int pair = blockIdx.x * P_BLK + pl;

    unsigned long long acc0[12], acc1[12];
    #pragma unroll
    for (int j = 0; j < 12; j++) { acc0[j] = 0ull; acc1[j] = 0ull; }

    const float4* w0 = (const float4*)sw + (2 * pl) * 40 + q * 10;
    const float4* w1 = (const float4*)sw + (2 * pl + 1) * 40 + q * 10;
    const ulonglong2* gq = (const ulonglong2*)(sg + (q * 2 + h) * REG_U64);

    #pragma unroll 2
    for (int g4 = 0; g4 < 10; g4++) {        // 10 float4 groups = 40 columns
        float4 wa = w0[g4];
        float4 wb = w1[g4];
        float was[4] = {wa.x, wa.y, wa.z, wa.w};
        float wbs[4] = {wb.x, wb.y, wb.z, wb.w};
        #pragma unroll
        for (int s = 0; s < 4; s++) {
            unsigned long long W0 = dup2(was[s]);
            unsigned long long W1 = dup2(wbs[s]);
            const ulonglong2* gr = gq + (g4 * 4 + s) * 6;
            #pragma unroll
            for (int m = 0; m < 6; m++) {
                ulonglong2 g = gr[m];
                fma2(acc0[2*m],     W0, g.x);
                fma2(acc0[2*m + 1], W0, g.y);
                fma2(acc1[2*m],     W1, g.x);
                fma2(acc1[2*m + 1], W1, g.y);
            }
        }
    }

    // Combine C-quarters across q (lane bits [1:0]); tree +1, +2.
    #pragma unroll
    for (int j = 0; j < 12; j++) {
        add2(acc0[j], shfl_dn_u64(acc0[j], 1));
        add2(acc1[j], shfl_dn_u64(acc1[j], 1));
        add2(acc0[j], shfl_dn_u64(acc0[j], 2));
        add2(acc1[j], shfl_dn_u64(acc1[j], 2));
    }

    if (q == 0 && pair < PAIRS) {
        finish(2 * pair,     h, acc0, X, out);
        finish(2 * pair + 1, h, acc1, X, out);
    }
}

// ---------------- launch ----------------
extern "C" void kernel_launch(void* const* d_in, const int* in_sizes, int n_in,
                              void* d_out, int out_size) {
    const float* X   = (const float*)d_in[0];
    const float* Vn  = (const float*)d_in[1];
    const float* r6  = (const float*)d_in[2];
    const float* W   = (const float*)d_in[3];
    const int*   idx = (const int*)d_in[4];   // JAX x64-disabled: int64 -> int32
    float* out = (float*)d_out;

    precompute_kernel<<<(Bq * Cq + 127) / 128, 128>>>(X, Vn, r6, idx);

    const int smem_bytes = V_BLK * Cq * 4 + 8 * REG_U64 * 8;   // 20480 + 30856
    cudaFuncSetAttribute(main_kernel,
                         cudaFuncAttributeMaxDynamicSharedMemorySize, smem_bytes);

    int grid = (PAIRS + P_BLK - 1) / P_BLK;   // 1563 blocks
    main_kernel<<<grid, NTHR, smem_bytes>>>(W, X, out);
}

// round 7
// speedup vs baseline: 4.3745x; 1.6343x over previous
#include <cuda_runtime.h>
#include <cuda_bf16.h>
#include <cstdint>

#define Bq 4
#define Vq 50000
#define Cq 160
#define V_CTA 64          // vertices per CTA (4 warps x m16)
#define NTHR 128
#define KS 10             // 160 / 16
#define NT 6              // 48 / 8
#define APAD 82           // u32 per A row (80 pairs + 2 pad)
#define ALO_OFF (64 * APAD)          // u32 offset of lo-table
#define SB_OFF  (2 * 64 * APAD)      // u32 offset of B frags in smem
#define SMEM_U32 (SB_OFF + KS * NT * 32 * 4)
#define SMEM_BYTES (SMEM_U32 * 4)    // 72704

// B operand fragments in gmem: u32 [ks][nt][lane][4] = (bhi0,bhi1,blo0,blo1)
__device__ __align__(16) unsigned int g_bfrag[KS * NT * 32 * 4];

// ---------------- Precompute: G -> mma .col B fragments (bf16 hi/lo) --------
__global__ void precompute_kernel(const float* __restrict__ X,
                                  const float* __restrict__ Vn,
                                  const float* __restrict__ r6,
                                  const int* __restrict__ idx) {
    int i = blockIdx.x * blockDim.x + threadIdx.x;
    if (i >= Bq * Cq) return;
    int b = i / Cq, c = i % Cq;

    const float* d6 = r6 + (size_t)(b * Cq + c) * 6;
    float a1x = d6[0], a1y = d6[1], a1z = d6[2];
    float a2x = d6[3], a2y = d6[4], a2z = d6[5];

    float n1 = fmaxf(sqrtf(a1x*a1x + a1y*a1y + a1z*a1z), 1e-8f);
    float b1x = a1x/n1, b1y = a1y/n1, b1z = a1z/n1;
    float dt = b1x*a2x + b1y*a2y + b1z*a2z;
    float px = a2x - dt*b1x, py = a2y - dt*b1y, pz = a2z - dt*b1z;
    float n2 = fmaxf(sqrtf(px*px + py*py + pz*pz), 1e-8f);
    float b2x = px/n2, b2y = py/n2, b2z = pz/n2;
    float b3x = b1y*b2z - b1z*b2y;
    float b3y = b1z*b2x - b1x*b2z;
    float b3z = b1x*b2y - b1y*b2x;

    float R[3][3] = {{b1x,b1y,b1z},{b2x,b2y,b2z},{b3x,b3y,b3z}};

    int vi = idx[c];
    vi = max(0, min(Vq - 1, vi));
    const float* xc = X + ((size_t)b * Vq + vi) * 3;
    float cen[3] = {xc[0], xc[1], xc[2]};
    const float* vn = Vn + (size_t)(b * Cq + c) * 3;

    float g[12];
    #pragma unroll
    for (int k = 0; k < 3; k++) {
        #pragma unroll
        for (int d = 0; d < 3; d++) g[k*3 + d] = R[k][d];
        g[9 + k] = cen[k] + vn[k]
                 - (R[k][0]*cen[0] + R[k][1]*cen[1] + R[k][2]*cen[2]);
    }

    // B[k=c][n=j*4+b] -> fragment slot
    int ks  = c >> 4, klo = c & 15;
    int reg = klo >> 3;            // b0 / b1
    int tig = (klo >> 1) & 3;
    int odd = klo & 1;             // low/high u16 inside the reg
    unsigned short* p16 = (unsigned short*)g_bfrag;

    #pragma unroll
    for (int j = 0; j < 12; j++) {
        int n = j * 4 + b;
        int lane = (n & 7) * 4 + tig;
        int slot = ((ks * NT + (n >> 3)) * 32 + lane) * 4;
        __nv_bfloat16 hi = __float2bfloat16_rn(g[j]);
        __nv_bfloat16 lo = __float2bfloat16_rn(g[j] - __bfloat162float(hi));
        p16[(slot + reg)     * 2 + odd] = __bfloat16_as_ushort(hi);
        p16[(slot + 2 + reg) * 2 + odd] = __bfloat16_as_ushort(lo);
    }
}

// ---------------- helpers ----------------
__device__ __forceinline__ uint32_t pack_bf16x2(float lo, float hi) {
    uint32_t r;   // first src operand -> upper half
    asm("cvt.rn.bf16x2.f32 %0, %1, %2;" : "=r"(r) : "f"(hi), "f"(lo));
    return r;
}
__device__ __forceinline__ void mma16816(float* d, const uint32_t* a,
                                         uint32_t b0, uint32_t b1) {
    asm volatile(
        "mma.sync.aligned.m16n8k16.row.col.f32.bf16.bf16.f32 "
        "{%0,%1,%2,%3}, {%4,%5,%6,%7}, {%8,%9}, {%0,%1,%2,%3};"
        : "+f"(d[0]), "+f"(d[1]), "+f"(d[2]), "+f"(d[3])
        : "r"(a[0]), "r"(a[1]), "r"(a[2]), "r"(a[3]), "r"(b0), "r"(b1));
}

// ---------------- Main kernel ----------------
__global__ void __launch_bounds__(NTHR, 3)
main_kernel(const float* __restrict__ W,
            const float* __restrict__ X,
            float* __restrict__ out) {
    extern __shared__ __align__(16) unsigned int smem[];
    unsigned int* sA = smem;               // Phi[64][82], Plo at +ALO_OFF
    unsigned int* sB = smem + SB_OFF;

    int tid = threadIdx.x, wid = tid >> 5, lane = tid & 31;
    int vbase = blockIdx.x * V_CTA;

    // Copy B fragments (30720B)
    {
        const uint4* src = (const uint4*)g_bfrag;
        uint4* dst = (uint4*)sB;
        #pragma unroll
        for (int i = tid; i < KS * NT * 32; i += NTHR) dst[i] = src[i];
    }
    // Stage W -> bf16 hi/lo pair tables
    for (int i = tid; i < V_CTA * 40; i += NTHR) {
        int v = i / 40, c4 = i % 40;
        int vg = min(vbase + v, Vq - 1);
        float4 w = ((const float4*)(W + (size_t)vg * Cq))[c4];

        uint32_t h01 = pack_bf16x2(w.x, w.y);
        float hx = __uint_as_float(h01 << 16);
        float hy = __uint_as_float(h01 & 0xFFFF0000u);
        uint32_t l01 = pack_bf16x2(w.x - hx, w.y - hy);

        uint32_t h23 = pack_bf16x2(w.z, w.w);
        float hz = __uint_as_float(h23 << 16);
        float hw = __uint_as_float(h23 & 0xFFFF0000u);
        uint32_t l23 = pack_bf16x2(w.z - hz, w.w - hw);

        int base = v * APAD + c4 * 2;
        sA[base] = h01;           sA[base + 1] = h23;
        sA[ALO_OFF + base] = l01; sA[ALO_OFF + base + 1] = l23;
    }
    __syncthreads();

    int g = lane >> 2, t = lane & 3;
    int rowA = (wid * 16 + g) * APAD;
    int rowB = (wid * 16 + g + 8) * APAD;

    float d[NT][4];
    #pragma unroll
    for (int nt = 0; nt < NT; nt++)
        #pragma unroll
        for (int r = 0; r < 4; r++) d[nt][r] = 0.0f;

    #pragma unroll 2
    for (int ks = 0; ks < KS; ks++) {
        int k2 = ks * 8 + t;
        uint32_t ah[4], al[4];
        ah[0] = sA[rowA + k2];     ah[1] = sA[rowB + k2];
        ah[2] = sA[rowA + k2 + 4]; ah[3] = sA[rowB + k2 + 4];
        al[0] = sA[ALO_OFF + rowA + k2];     al[1] = sA[ALO_OFF + rowB + k2];
        al[2] = sA[ALO_OFF + rowA + k2 + 4]; al[3] = sA[ALO_OFF + rowB + k2 + 4];
        #pragma unroll
        for (int nt = 0; nt < NT; nt++) {
            uint4 bb = *(const uint4*)&sB[((ks * NT + nt) * 32 + lane) * 4];
            mma16816(d[nt], ah, bb.x, bb.y);   // hi * hi
            mma16816(d[nt], ah, bb.z, bb.w);   // hi * lo
            mma16816(d[nt], al, bb.x, bb.y);   // lo * hi
        }
    }

    __syncthreads();   // done reading sA; reuse as D scratch
    float* Dsm = (float*)sA;    // [64][49]
    #pragma unroll
    for (int nt = 0; nt < NT; nt++) {
        int col = nt * 8 + 2 * t;
        int r0 = (wid * 16 + g) * 49, r1 = (wid * 16 + g + 8) * 49;
        Dsm[r0 + col] = d[nt][0]; Dsm[r0 + col + 1] = d[nt][1];
        Dsm[r1 + col] = d[nt][2]; Dsm[r1 + col + 1] = d[nt][3];
    }
    __syncthreads();

    // Epilogue: thread handles vertex vl = tid>>1, batches {2*(tid&1), +1}
    int vl = tid >> 1;
    int v = vbase + vl;
    if (v < Vq) {
        #pragma unroll
        for (int b2 = 0; b2 < 2; b2++) {
            int b = 2 * (tid & 1) + b2;
            float m[12];
            #pragma unroll
            for (int j = 0; j < 12; j++) m[j] = Dsm[vl * 49 + j * 4 + b];
            const float* xp = X + ((size_t)b * Vq + v) * 3;
            float x0 = xp[0], x1 = xp[1], x2 = xp[2];
            float* op = out + ((size_t)b * Vq + v) * 3;
            op[0] = m[9]  + m[0]*x0 + m[1]*x1 + m[2]*x2;
            op[1] = m[10] + m[3]*x0 + m[4]*x1 + m[5]*x2;
            op[2] = m[11] + m[6]*x0 + m[7]*x1 + m[8]*x2;
        }
    }
}

// ---------------- launch ----------------
extern "C" void kernel_launch(void* const* d_in, const int* in_sizes, int n_in,
                              void* d_out, int out_size) {
    const float* X   = (const float*)d_in[0];
    const float* Vn  = (const float*)d_in[1];
    const float* r6  = (const float*)d_in[2];
    const float* W   = (const float*)d_in[3];
    const int*   idx = (const int*)d_in[4];   // JAX x64-disabled: int64 -> int32
    float* out = (float*)d_out;

    precompute_kernel<<<(Bq * Cq + 127) / 128, 128>>>(X, Vn, r6, idx);

    cudaFuncSetAttribute(main_kernel,
                         cudaFuncAttributeMaxDynamicSharedMemorySize, SMEM_BYTES);
    int grid = (Vq + V_CTA - 1) / V_CTA;    // 782
    main_kernel<<<grid, NTHR, SMEM_BYTES>>>(W, X, out);
}

// round 8
// speedup vs baseline: 6.4720x; 1.4795x over previous
#include <cuda_runtime.h>
#include <cuda_bf16.h>
#include <cstdint>

#define Bq 4
#define Vq 50000
#define Cq 160
#define V_CTA 64          // vertices per CTA (4 warps x m16)
#define NTHR 128
#define KS 10             // 160 / 16
#define NT 6              // 48 / 8
#define SB_U32 (KS * NT * 32 * 4)     // 7680 u32 = 30720B
#define SMEM_BYTES (SB_U32 * 4)

// B operand fragments in gmem: u32 [ks][nt][lane][4] = (bhi0,bhi1,blo0,blo1)
// k-permutation: thread t of the mma owns ACTUAL k = ks*16 + 4t .. 4t+3,
// mapped to fragment positions (b0: j=0,1) (b1: j=2,3).
__device__ __align__(16) unsigned int g_bfrag[SB_U32];

// ---------------- Precompute: G -> permuted .col B fragments (bf16 hi/lo) ---
__global__ void precompute_kernel(const float* __restrict__ X,
                                  const float* __restrict__ Vn,
                                  const float* __restrict__ r6,
                                  const int* __restrict__ idx) {
    int i = blockIdx.x * blockDim.x + threadIdx.x;
    if (i >= Bq * Cq) return;
    int b = i / Cq, c = i % Cq;

    const float* d6 = r6 + (size_t)(b * Cq + c) * 6;
    float a1x = d6[0], a1y = d6[1], a1z = d6[2];
    float a2x = d6[3], a2y = d6[4], a2z = d6[5];

    float n1 = fmaxf(sqrtf(a1x*a1x + a1y*a1y + a1z*a1z), 1e-8f);
    float b1x = a1x/n1, b1y = a1y/n1, b1z = a1z/n1;
    float dt = b1x*a2x + b1y*a2y + b1z*a2z;
    float px = a2x - dt*b1x, py = a2y - dt*b1y, pz = a2z - dt*b1z;
    float n2 = fmaxf(sqrtf(px*px + py*py + pz*pz), 1e-8f);
    float b2x = px/n2, b2y = py/n2, b2z = pz/n2;
    float b3x = b1y*b2z - b1z*b2y;
    float b3y = b1z*b2x - b1x*b2z;
    float b3z = b1x*b2y - b1y*b2x;

    float R[3][3] = {{b1x,b1y,b1z},{b2x,b2y,b2z},{b3x,b3y,b3z}};

    int vi = idx[c];
    vi = max(0, min(Vq - 1, vi));
    const float* xc = X + ((size_t)b * Vq + vi) * 3;
    float cen[3] = {xc[0], xc[1], xc[2]};
    const float* vn = Vn + (size_t)(b * Cq + c) * 3;

    float g[12];
    #pragma unroll
    for (int k = 0; k < 3; k++) {
        #pragma unroll
        for (int d = 0; d < 3; d++) g[k*3 + d] = R[k][d];
        g[9 + k] = cen[k] + vn[k]
                 - (R[k][0]*cen[0] + R[k][1]*cen[1] + R[k][2]*cen[2]);
    }

    // actual k = c: ks = c>>4, within-step klo = c&15; t = klo>>2, j = klo&3.
    // j in {0,1} -> b0-reg element j; j in {2,3} -> b1-reg element j-2.
    int ks  = c >> 4, klo = c & 15;
    int t   = klo >> 2;
    int j   = klo & 3;
    int reg = j >> 1;            // 0 -> b0, 1 -> b1
    int elem = j & 1;
    unsigned short* p16 = (unsigned short*)g_bfrag;

    #pragma unroll
    for (int jj = 0; jj < 12; jj++) {
        int n = jj * 4 + b;
        int lane = (n & 7) * 4 + t;
        int slot = ((ks * NT + (n >> 3)) * 32 + lane) * 4;
        __nv_bfloat16 hi = __float2bfloat16_rn(g[jj]);
        __nv_bfloat16 lo = __float2bfloat16_rn(g[jj] - __bfloat162float(hi));
        p16[(slot + reg)     * 2 + elem] = __bfloat16_as_ushort(hi);
        p16[(slot + 2 + reg) * 2 + elem] = __bfloat16_as_ushort(lo);
    }
}

// ---------------- helpers ----------------
__device__ __forceinline__ uint32_t pack_bf16x2(float lo, float hi) {
    uint32_t r;   // first src operand -> upper half
    asm("cvt.rn.bf16x2.f32 %0, %1, %2;" : "=r"(r) : "f"(hi), "f"(lo));
    return r;
}
__device__ __forceinline__ void mma16816(float* d, const uint32_t* a,
                                         uint32_t b0, uint32_t b1) {
    asm volatile(
        "mma.sync.aligned.m16n8k16.row.col.f32.bf16.bf16.f32 "
        "{%0,%1,%2,%3}, {%4,%5,%6,%7}, {%8,%9}, {%0,%1,%2,%3};"
        : "+f"(d[0]), "+f"(d[1]), "+f"(d[2]), "+f"(d[3])
        : "r"(a[0]), "r"(a[1]), "r"(a[2]), "r"(a[3]), "r"(b0), "r"(b1));
}
// split float4 into (hi01, hi23, lo01, lo23) bf16x2 regs
__device__ __forceinline__ void split4(float4 w, uint32_t& h01, uint32_t& h23,
                                       uint32_t& l01, uint32_t& l23) {
    h01 = pack_bf16x2(w.x, w.y);
    float hx = __uint_as_float(h01 << 16);
    float hy = __uint_as_float(h01 & 0xFFFF0000u);
    l01 = pack_bf16x2(w.x - hx, w.y - hy);
    h23 = pack_bf16x2(w.z, w.w);
    float hz = __uint_as_float(h23 << 16);
    float hw = __uint_as_float(h23 & 0xFFFF0000u);
    l23 = pack_bf16x2(w.z - hz, w.w - hw);
}

// ---------------- Main kernel ----------------
__global__ void __launch_bounds__(NTHR, 5)
main_kernel(const float* __restrict__ W,
            const float* __restrict__ X,
            float* __restrict__ out) {
    extern __shared__ __align__(16) unsigned int smem[];
    unsigned int* sB = smem;

    int tid = threadIdx.x, wid = tid >> 5, lane = tid & 31;
    int g = lane >> 2, t = lane & 3;
    int vbase = blockIdx.x * V_CTA;

    // gmem rows this thread covers (clamped for tail CTA)
    int r0 = min(vbase + wid * 16 + g,     Vq - 1);
    int r1 = min(vbase + wid * 16 + g + 8, Vq - 1);
    const float* w0p = W + (size_t)r0 * Cq + 4 * t;
    const float* w1p = W + (size_t)r1 * Cq + 4 * t;

    // Prefetch kstep 0 A-data before anything else (fires LDGs early)
    float4 wa = *(const float4*)(w0p);
    float4 wb = *(const float4*)(w1p);

    // Copy B fragments to smem (30720B)
    {
        const uint4* src = (const uint4*)g_bfrag;
        uint4* dst = (uint4*)sB;
        #pragma unroll
        for (int i = tid; i < SB_U32 / 4; i += NTHR) dst[i] = src[i];
    }
    __syncthreads();

    float d[NT][4];
    #pragma unroll
    for (int nt = 0; nt < NT; nt++)
        #pragma unroll
        for (int r = 0; r < 4; r++) d[nt][r] = 0.0f;

    #pragma unroll
    for (int ks = 0; ks < KS; ks++) {
        // prefetch next kstep
        float4 na, nb;
        if (ks + 1 < KS) {
            na = *(const float4*)(w0p + (ks + 1) * 16);
            nb = *(const float4*)(w1p + (ks + 1) * 16);
        }
        uint32_t ah[4], al[4];
        split4(wa, ah[0], ah[2], al[0], al[2]);   // row g:  k-pairs (4t,4t+1),(4t+2,4t+3)
        split4(wb, ah[1], ah[3], al[1], al[3]);   // row g+8
        #pragma unroll
        for (int nt = 0; nt < NT; nt++) {
            uint4 bb = *(const uint4*)&sB[((ks * NT + nt) * 32 + lane) * 4];
            mma16816(d[nt], ah, bb.x, bb.y);   // hi * hi
            mma16816(d[nt], ah, bb.z, bb.w);   // hi * lo
            mma16816(d[nt], al, bb.x, bb.y);   // lo * hi
        }
        wa = na; wb = nb;
    }

    __syncthreads();   // done reading sB; reuse as D scratch [64][49]
    float* Dsm = (float*)sB;
    #pragma unroll
    for (int nt = 0; nt < NT; nt++) {
        int col = nt * 8 + 2 * t;
        int q0 = (wid * 16 + g) * 49, q1 = (wid * 16 + g + 8) * 49;
        Dsm[q0 + col] = d[nt][0]; Dsm[q0 + col + 1] = d[nt][1];
        Dsm[q1 + col] = d[nt][2]; Dsm[q1 + col + 1] = d[nt][3];
    }
    __syncthreads();

    // Epilogue: thread handles vertex vl = tid>>1, batches {2*(tid&1), +1}
    int vl = tid >> 1;
    int v = vbase + vl;
    if (v < Vq) {
        #pragma unroll
        for (int b2 = 0; b2 < 2; b2++) {
            int b = 2 * (tid & 1) + b2;
            float m[12];
            #pragma unroll
            for (int j = 0; j < 12; j++) m[j] = Dsm[vl * 49 + j * 4 + b];
            const float* xp = X + ((size_t)b * Vq + v) * 3;
            float x0 = xp[0], x1 = xp[1], x2 = xp[2];
            float* op = out + ((size_t)b * Vq + v) * 3;
            op[0] = m[9]  + m[0]*x0 + m[1]*x1 + m[2]*x2;
            op[1] = m[10] + m[3]*x0 + m[4]*x1 + m[5]*x2;
            op[2] = m[11] + m[6]*x0 + m[7]*x1 + m[8]*x2;
        }
    }
}

// ---------------- launch ----------------
extern "C" void kernel_launch(void* const* d_in, const int* in_sizes, int n_in,
                              void* d_out, int out_size) {
    const float* X   = (const float*)d_in[0];
    const float* Vn  = (const float*)d_in[1];
    const float* r6  = (const float*)d_in[2];
    const float* W   = (const float*)d_in[3];
    const int*   idx = (const int*)d_in[4];   // JAX x64-disabled: int64 -> int32
    float* out = (float*)d_out;

    precompute_kernel<<<(Bq * Cq + 127) / 128, 128>>>(X, Vn, r6, idx);

    cudaFuncSetAttribute(main_kernel,
                         cudaFuncAttributeMaxDynamicSharedMemorySize, SMEM_BYTES);
    int grid = (Vq + V_CTA - 1) / V_CTA;    // 782
    main_kernel<<<grid, NTHR, SMEM_BYTES>>>(W, X, out);
}

// round 9
// speedup vs baseline: 7.4763x; 1.1552x over previous
#include <cuda_runtime.h>
#include <cuda_bf16.h>
#include <cstdint>

#define Bq 4
#define Vq 50000
#define Cq 160
#define V_CTA 128         // vertices per CTA (4 warps x m32)
#define NTHR 128
#define KS 10             // 160 / 16
#define NT 6              // 48 / 8
#define SB_U32 (KS * NT * 32 * 4)     // 7680 u32 = 30720B
#define SMEM_BYTES (SB_U32 * 4)       // >= 128*49*4 D scratch

// B operand fragments in gmem: u32 [ks][nt][lane][4] = (bhi0,bhi1,blo0,blo1)
// k-permutation: thread t of the mma owns ACTUAL k = ks*16 + 4t .. 4t+3.
__device__ __align__(16) unsigned int g_bfrag[SB_U32];

// ---------------- Precompute: G -> permuted .col B fragments (bf16 hi/lo) ---
__global__ void precompute_kernel(const float* __restrict__ X,
                                  const float* __restrict__ Vn,
                                  const float* __restrict__ r6,
                                  const int* __restrict__ idx) {
    int i = blockIdx.x * blockDim.x + threadIdx.x;
    if (i >= Bq * Cq) return;
    int b = i / Cq, c = i % Cq;

    const float* d6 = r6 + (size_t)(b * Cq + c) * 6;
    float a1x = d6[0], a1y = d6[1], a1z = d6[2];
    float a2x = d6[3], a2y = d6[4], a2z = d6[5];

    float n1 = fmaxf(sqrtf(a1x*a1x + a1y*a1y + a1z*a1z), 1e-8f);
    float b1x = a1x/n1, b1y = a1y/n1, b1z = a1z/n1;
    float dt = b1x*a2x + b1y*a2y + b1z*a2z;
    float px = a2x - dt*b1x, py = a2y - dt*b1y, pz = a2z - dt*b1z;
    float n2 = fmaxf(sqrtf(px*px + py*py + pz*pz), 1e-8f);
    float b2x = px/n2, b2y = py/n2, b2z = pz/n2;
    float b3x = b1y*b2z - b1z*b2y;
    float b3y = b1z*b2x - b1x*b2z;
    float b3z = b1x*b2y - b1y*b2x;

    float R[3][3] = {{b1x,b1y,b1z},{b2x,b2y,b2z},{b3x,b3y,b3z}};

    int vi = idx[c];
    vi = max(0, min(Vq - 1, vi));
    const float* xc = X + ((size_t)b * Vq + vi) * 3;
    float cen[3] = {xc[0], xc[1], xc[2]};
    const float* vn = Vn + (size_t)(b * Cq + c) * 3;

    float g[12];
    #pragma unroll
    for (int k = 0; k < 3; k++) {
        #pragma unroll
        for (int d = 0; d < 3; d++) g[k*3 + d] = R[k][d];
        g[9 + k] = cen[k] + vn[k]
                 - (R[k][0]*cen[0] + R[k][1]*cen[1] + R[k][2]*cen[2]);
    }

    int ks  = c >> 4, klo = c & 15;
    int t   = klo >> 2;
    int j   = klo & 3;
    int reg = j >> 1;
    int elem = j & 1;
    unsigned short* p16 = (unsigned short*)g_bfrag;

    #pragma unroll
    for (int jj = 0; jj < 12; jj++) {
        int n = jj * 4 + b;
        int lane = (n & 7) * 4 + t;
        int slot = ((ks * NT + (n >> 3)) * 32 + lane) * 4;
        __nv_bfloat16 hi = __float2bfloat16_rn(g[jj]);
        __nv_bfloat16 lo = __float2bfloat16_rn(g[jj] - __bfloat162float(hi));
        p16[(slot + reg)     * 2 + elem] = __bfloat16_as_ushort(hi);
        p16[(slot + 2 + reg) * 2 + elem] = __bfloat16_as_ushort(lo);
    }
}

// ---------------- helpers ----------------
__device__ __forceinline__ uint32_t pack_bf16x2(float lo, float hi) {
    uint32_t r;
    asm("cvt.rn.bf16x2.f32 %0, %1, %2;" : "=r"(r) : "f"(hi), "f"(lo));
    return r;
}
__device__ __forceinline__ void mma16816(float* d, const uint32_t* a,
                                         uint32_t b0, uint32_t b1) {
    asm volatile(
        "mma.sync.aligned.m16n8k16.row.col.f32.bf16.bf16.f32 "
        "{%0,%1,%2,%3}, {%4,%5,%6,%7}, {%8,%9}, {%0,%1,%2,%3};"
        : "+f"(d[0]), "+f"(d[1]), "+f"(d[2]), "+f"(d[3])
        : "r"(a[0]), "r"(a[1]), "r"(a[2]), "r"(a[3]), "r"(b0), "r"(b1));
}
__device__ __forceinline__ void split4(float4 w, uint32_t& h01, uint32_t& h23,
                                       uint32_t& l01, uint32_t& l23) {
    h01 = pack_bf16x2(w.x, w.y);
    float hx = __uint_as_float(h01 << 16);
    float hy = __uint_as_float(h01 & 0xFFFF0000u);
    l01 = pack_bf16x2(w.x - hx, w.y - hy);
    h23 = pack_bf16x2(w.z, w.w);
    float hz = __uint_as_float(h23 << 16);
    float hw = __uint_as_float(h23 & 0xFFFF0000u);
    l23 = pack_bf16x2(w.z - hz, w.w - hw);
}

// ---------------- Main kernel: m32 per warp ----------------
__global__ void __launch_bounds__(NTHR, 3)
main_kernel(const float* __restrict__ W,
            const float* __restrict__ X,
            float* __restrict__ out) {
    extern __shared__ __align__(16) unsigned int smem[];
    unsigned int* sB = smem;

    int tid = threadIdx.x, wid = tid >> 5, lane = tid & 31;
    int g = lane >> 2, t = lane & 3;
    int vbase = blockIdx.x * V_CTA;

    // 4 fragment row-groups per warp: g, g+8 (tile0), g+16, g+24 (tile1)
    const float* wp[4];
    #pragma unroll
    for (int i = 0; i < 4; i++) {
        int r = min(vbase + wid * 32 + g + 8 * i, Vq - 1);
        wp[i] = W + (size_t)r * Cq + 4 * t;
    }

    // Prefetch kstep 0
    float4 cur0 = *(const float4*)wp[0];
    float4 cur1 = *(const float4*)wp[1];
    float4 cur2 = *(const float4*)wp[2];
    float4 cur3 = *(const float4*)wp[3];

    // Copy B fragments to smem (30720B)
    {
        const uint4* src = (const uint4*)g_bfrag;
        uint4* dst = (uint4*)sB;
        #pragma unroll
        for (int i = tid; i < SB_U32 / 4; i += NTHR) dst[i] = src[i];
    }
    __syncthreads();

    float d0[NT][4], d1[NT][4];
    #pragma unroll
    for (int nt = 0; nt < NT; nt++)
        #pragma unroll
        for (int r = 0; r < 4; r++) { d0[nt][r] = 0.0f; d1[nt][r] = 0.0f; }

    #pragma unroll
    for (int ks = 0; ks < KS; ks++) {
        float4 n0, n1, n2, n3;
        if (ks + 1 < KS) {
            n0 = *(const float4*)(wp[0] + (ks + 1) * 16);
            n1 = *(const float4*)(wp[1] + (ks + 1) * 16);
            n2 = *(const float4*)(wp[2] + (ks + 1) * 16);
            n3 = *(const float4*)(wp[3] + (ks + 1) * 16);
        }
        uint32_t ah0[4], al0[4], ah1[4], al1[4];
        split4(cur0, ah0[0], ah0[2], al0[0], al0[2]);
        split4(cur1, ah0[1], ah0[3], al0[1], al0[3]);
        split4(cur2, ah1[0], ah1[2], al1[0], al1[2]);
        split4(cur3, ah1[1], ah1[3], al1[1], al1[3]);
        #pragma unroll
        for (int nt = 0; nt < NT; nt++) {
            uint4 bb = *(const uint4*)&sB[((ks * NT + nt) * 32 + lane) * 4];
            mma16816(d0[nt], ah0, bb.x, bb.y);   // hi*hi
            mma16816(d0[nt], ah0, bb.z, bb.w);   // hi*lo
            mma16816(d0[nt], al0, bb.x, bb.y);   // lo*hi
            mma16816(d1[nt], ah1, bb.x, bb.y);
            mma16816(d1[nt], ah1, bb.z, bb.w);
            mma16816(d1[nt], al1, bb.x, bb.y);
        }
        cur0 = n0; cur1 = n1; cur2 = n2; cur3 = n3;
    }

    __syncthreads();   // done reading sB; reuse as D scratch [128][49]
    float* Dsm = (float*)sB;
    #pragma unroll
    for (int nt = 0; nt < NT; nt++) {
        int col = nt * 8 + 2 * t;
        int q0 = (wid * 32 + g) * 49;
        int q1 = (wid * 32 + g + 8) * 49;
        int q2 = (wid * 32 + g + 16) * 49;
        int q3 = (wid * 32 + g + 24) * 49;
        Dsm[q0 + col] = d0[nt][0]; Dsm[q0 + col + 1] = d0[nt][1];
        Dsm[q1 + col] = d0[nt][2]; Dsm[q1 + col + 1] = d0[nt][3];
        Dsm[q2 + col] = d1[nt][0]; Dsm[q2 + col + 1] = d1[nt][1];
        Dsm[q3 + col] = d1[nt][2]; Dsm[q3 + col + 1] = d1[nt][3];
    }
    __syncthreads();

    // Epilogue: thread tid owns vertex vbase+tid, all 4 batches
    int v = vbase + tid;
    if (v < Vq) {
        float m[12];
        #pragma unroll
        for (int b = 0; b < Bq; b++) {
            #pragma unroll
            for (int j = 0; j < 12; j++) m[j] = Dsm[tid * 49 + j * 4 + b];
            const float* xp = X + ((size_t)b * Vq + v) * 3;
            float x0 = xp[0], x1 = xp[1], x2 = xp[2];
            float* op = out + ((size_t)b * Vq + v) * 3;
            op[0] = m[9]  + m[0]*x0 + m[1]*x1 + m[2]*x2;
            op[1] = m[10] + m[3]*x0 + m[4]*x1 + m[5]*x2;
            op[2] = m[11] + m[6]*x0 + m[7]*x1 + m[8]*x2;
        }
    }
}

// ---------------- launch ----------------
extern "C" void kernel_launch(void* const* d_in, const int* in_sizes, int n_in,
                              void* d_out, int out_size) {
    const float* X   = (const float*)d_in[0];
    const float* Vn  = (const float*)d_in[1];
    const float* r6  = (const float*)d_in[2];
    const float* W   = (const float*)d_in[3];
    const int*   idx = (const int*)d_in[4];   // JAX x64-disabled: int64 -> int32
    float* out = (float*)d_out;

    precompute_kernel<<<(Bq * Cq + 127) / 128, 128>>>(X, Vn, r6, idx);

    cudaFuncSetAttribute(main_kernel,
                         cudaFuncAttributeMaxDynamicSharedMemorySize, SMEM_BYTES);
    int grid = (Vq + V_CTA - 1) / V_CTA;    // 391
    main_kernel<<<grid, NTHR, SMEM_BYTES>>>(W, X, out);
}